// round 9
// baseline (speedup 1.0000x reference)
#include <cuda_runtime.h>
#include <cstdint>
#include <cstddef>

// Problem dims
#define BB 64
#define TT 256
#define DD 512
#define HH 1024
#define G4 4096
#define NCTA 128
#define UPC 8     // units per CTA (32 gate-cols)
// SMEM strides
#define US_STRIDE 1028
#define AS_STRIDE 36
#define WS_STRIDE 72
// LSTM h chunking
#define KCH 64
#define NCH 16
#define HCH_STRIDE 68
#define W2S_STRIDE 40
#define HSLOT_FLOATS (64*HCH_STRIDE)     // 4352
#define WSLOT_FLOATS (64*W2S_STRIDE)     // 2560
#define PLANE_FLOATS (64*33)             // 2112

#define GEMM_STAGE_FLOATS (128*AS_STRIDE + 32*WS_STRIDE)
#define GEMM_SMEM_BYTES  (3*GEMM_STAGE_FLOATS*4)                  // 82944

// fused scan: Us + 3 h slots + 3 w2 slots (planes overlay the slot region)
#define FUSED_SMEM_FLOATS (32*US_STRIDE + 3*HSLOT_FLOATS + 3*WSLOT_FLOATS)   // 53632
#define FUSED_SMEM_BYTES  (FUSED_SMEM_FLOATS*4)                   // 214528
// plain scan (layer 2): Us + 4 h slots
#define PLAIN_SMEM_FLOATS (32*US_STRIDE + 4*HSLOT_FLOATS)
#define PLAIN_SMEM_BYTES  (PLAIN_SMEM_FLOATS*4)                   // 201216

// ---------------- scratch ----------------
__device__ float    g_xz[(size_t)TT*BB*G4];     // layer-1 gate pre-acts (from gemm1)
__device__ float    g_xz2[(size_t)TT*BB*G4];    // layer-2 gate pre-acts (from fused scan)
__device__ float    g_xr[(size_t)BB*TT*DD];
__device__ float    g_W1r[(size_t)DD*G4];
__device__ float    g_W2r[(size_t)HH*G4];
__device__ float    g_h1[2*BB*HH];
__device__ float    g_h2[2*BB*HH];
__device__ unsigned g_flag[2][NCTA * 32];
__device__ unsigned g_epoch[2];

// ---------------- helpers ----------------
__device__ __forceinline__ unsigned f2tf(float f) {
    unsigned u; asm("cvt.rna.tf32.f32 %0, %1;" : "=r"(u) : "f"(f)); return u;
}
__device__ __forceinline__ void mma_tf32(float c[4], const unsigned a[4], unsigned b0, unsigned b1) {
    asm volatile(
        "mma.sync.aligned.m16n8k8.row.col.f32.tf32.tf32.f32 "
        "{%0,%1,%2,%3}, {%4,%5,%6,%7}, {%8,%9}, {%0,%1,%2,%3};\n"
        : "+f"(c[0]), "+f"(c[1]), "+f"(c[2]), "+f"(c[3])
        : "r"(a[0]), "r"(a[1]), "r"(a[2]), "r"(a[3]), "r"(b0), "r"(b1));
}
__device__ __forceinline__ void cp16_ca(void* smem_dst, const float* gsrc) {
    unsigned d = (unsigned)__cvta_generic_to_shared(smem_dst);
    asm volatile("cp.async.ca.shared.global [%0], [%1], 16;\n" :: "r"(d), "l"(gsrc) : "memory");
}
__device__ __forceinline__ void cp16_cg(void* smem_dst, const float* gsrc) {
    unsigned d = (unsigned)__cvta_generic_to_shared(smem_dst);
    asm volatile("cp.async.cg.shared.global [%0], [%1], 16;\n" :: "r"(d), "l"(gsrc) : "memory");
}
__device__ __forceinline__ void cp_commit() { asm volatile("cp.async.commit_group;\n" ::: "memory"); }
__device__ __forceinline__ void cp_wait1() { asm volatile("cp.async.wait_group 1;\n" ::: "memory"); }
__device__ __forceinline__ void cp_wait2() { asm volatile("cp.async.wait_group 2;\n" ::: "memory"); }
__device__ __forceinline__ float sigf(float x) { return 1.f / (1.f + __expf(-x)); }

// ---------------- init ----------------
__global__ void init_zero() {
    int idx = blockIdx.x * blockDim.x + threadIdx.x;
    int stride = gridDim.x * blockDim.x;
    for (int i = idx; i < 2 * BB * HH; i += stride) { g_h1[i] = 0.f; g_h2[i] = 0.f; }
    for (int i = idx; i < NCTA * 32; i += stride) { g_flag[0][i] = 0u; g_flag[1][i] = 0u; }
    if (idx == 0) { g_epoch[0] = 0u; g_epoch[1] = 0u; }
}

// ---------------- pre-round fp32 -> tf32 ----------------
__global__ void __launch_bounds__(256)
cvt_round(const float* __restrict__ src, int which, int n4) {
    float* dst = (which == 0) ? g_xr : (which == 1) ? g_W1r : g_W2r;
    int idx = blockIdx.x * blockDim.x + threadIdx.x;
    int stride = gridDim.x * blockDim.x;
    const float4* s4 = (const float4*)src;
    float4* d4 = (float4*)dst;
    for (int i = idx; i < n4; i += stride) {
        float4 v = s4[i];
        v.x = __uint_as_float(f2tf(v.x));
        v.y = __uint_as_float(f2tf(v.y));
        v.z = __uint_as_float(f2tf(v.z));
        v.w = __uint_as_float(f2tf(v.w));
        d4[i] = v;
    }
}

// ---------------- gemm1: g_xz[t*B+b] = x(b,t) @ W1 + b1 ----------------
__global__ void __launch_bounds__(256)
gemm_xw(const float* __restrict__ bias)
{
    extern __shared__ float sm[];
    const float* A = g_xr;
    const float* W = g_W1r;
    const int K = DD, sAb = TT * DD, sAt = DD;

    const int tid = threadIdx.x;
    const int lane = tid & 31, w = tid >> 5;
    const int wm = w & 3, wn = w >> 2;
    const int bn = blockIdx.x * 64;
    const int bm = blockIdx.y * 128;

    float cf[2][4][4];
#pragma unroll
    for (int i = 0; i < 2; i++)
#pragma unroll
        for (int j = 0; j < 4; j++)
#pragma unroll
            for (int q = 0; q < 4; q++) cf[i][j][q] = 0.f;

    const int KB = K >> 5;

    auto dostage = [&](int slot, int kb) {
        float* As = sm + slot * GEMM_STAGE_FLOATS;
        float* Ws = As + 128 * AS_STRIDE;
        const int k0 = kb * 32;
#pragma unroll
        for (int i = 0; i < 4; i++) {
            int idx = i * 256 + tid;
            int r = idx >> 3, s = idx & 7;
            int m = bm + r;
            const float* src = A + (size_t)(m & 63) * sAb + (size_t)(m >> 6) * sAt + k0 + s * 4;
            cp16_ca(&As[r * AS_STRIDE + s * 4], src);
        }
#pragma unroll
        for (int i = 0; i < 2; i++) {
            int idx = i * 256 + tid;
            int r = idx >> 4, s = idx & 15;
            const float* src = W + (size_t)(k0 + r) * G4 + bn + s * 4;
            cp16_ca(&Ws[r * WS_STRIDE + s * 4], src);
        }
    };

    dostage(0, 0); cp_commit();
    dostage(1, 1); cp_commit();

    const int lr = lane >> 2, lc = lane & 3;

    for (int kb = 0; kb < KB; kb++) {
        cp_wait1();
        __syncthreads();
        if (kb + 2 < KB) dostage((kb + 2) % 3, kb + 2);
        cp_commit();
        const float* as = sm + (kb % 3) * GEMM_STAGE_FLOATS;
        const float* ws = as + 128 * AS_STRIDE;
#pragma unroll
        for (int k8 = 0; k8 < 4; k8++) {
            unsigned a[2][4];
#pragma unroll
            for (int mt = 0; mt < 2; mt++) {
                int r0 = wm * 32 + mt * 16 + lr;
                a[mt][0] = __float_as_uint(as[r0 * AS_STRIDE + k8 * 8 + lc]);
                a[mt][1] = __float_as_uint(as[(r0 + 8) * AS_STRIDE + k8 * 8 + lc]);
                a[mt][2] = __float_as_uint(as[r0 * AS_STRIDE + k8 * 8 + lc + 4]);
                a[mt][3] = __float_as_uint(as[(r0 + 8) * AS_STRIDE + k8 * 8 + lc + 4]);
            }
#pragma unroll
            for (int nt = 0; nt < 4; nt++) {
                int c0 = wn * 32 + nt * 8 + lr;
                unsigned b0 = __float_as_uint(ws[(k8 * 8 + lc) * WS_STRIDE + c0]);
                unsigned b1 = __float_as_uint(ws[(k8 * 8 + lc + 4) * WS_STRIDE + c0]);
#pragma unroll
                for (int mt = 0; mt < 2; mt++) mma_tf32(cf[mt][nt], a[mt], b0, b1);
            }
        }
    }

#pragma unroll
    for (int mt = 0; mt < 2; mt++) {
#pragma unroll
        for (int nt = 0; nt < 4; nt++) {
            int gr = bm + wm * 32 + mt * 16 + lr;
            int gc = bn + wn * 32 + nt * 8 + 2 * lc;
            float bv0 = bias[gc], bv1 = bias[gc + 1];
            float2 v;
            v.x = cf[mt][nt][0] + bv0; v.y = cf[mt][nt][1] + bv1;
            *(float2*)&g_xz[(size_t)gr * G4 + gc] = v;
            v.x = cf[mt][nt][2] + bv0; v.y = cf[mt][nt][3] + bv1;
            *(float2*)&g_xz[(size_t)(gr + 8) * G4 + gc] = v;
        }
    }
}

// ================= FUSED layer-1 scan: lstm1 + xz2 = h1[t]@W2 =================
// smem: Us[32][1028] | Hst 3x[64][68] | W2s 3x[64][40]; planes overlay Hst/W2s.
__device__ __forceinline__ void fill_slot_f(const float* hr, const float* W2r, int ch, int u0,
                                            float* hslot, float* wslot, int tid) {
#pragma unroll
    for (int i = 0; i < 4; i++) {   // h: 64 rows x 16 segs
        int idx = i * 256 + tid;
        int r = idx >> 4, s = idx & 15;
        cp16_cg(hslot + r * HCH_STRIDE + s * 4, hr + (size_t)r * HH + ch * KCH + s * 4);
    }
#pragma unroll
    for (int i = 0; i < 2; i++) {   // W2 chunk: 64 k-rows x 8 segs (4 gates x 2 halves)
        int idx = i * 256 + tid;
        int kk = idx >> 3, seg = idx & 7;
        const float* src = W2r + (size_t)(ch * KCH + kk) * G4 + (seg >> 1) * HH + u0 + (seg & 1) * 4;
        cp16_ca(wslot + kk * W2S_STRIDE + (seg >> 1) * 8 + (seg & 1) * 4, src);
    }
}

__global__ void __launch_bounds__(256)
lstm_fused(const float* __restrict__ U, const float* __restrict__ b2)
{
    extern __shared__ float sm[];
    float* Us  = sm;
    float* Hst = Us + 32 * US_STRIDE;
    float* W2s = Hst + 3 * HSLOT_FLOATS;
    float* PL  = Hst;                    // plane overlay

    const float* W2r = g_W2r;
    float* hbuf = g_h1;
    volatile unsigned* flags = g_flag[0];
    volatile unsigned* epoch = &g_epoch[0];

    const int tid = threadIdx.x, lane = tid & 31, wid = tid >> 5;
    const int u0 = blockIdx.x * UPC;
    const int lr = lane >> 2, lc = lane & 3;
    const int klocal = wid * 8;

    for (int idx = tid; idx < 32 * HH; idx += 256) {
        int k = idx >> 5, c = idx & 31;
        int gcol = (c >> 3) * HH + u0 + (c & 7);
        Us[c * US_STRIDE + k] = __uint_as_float(f2tf(U[(size_t)k * G4 + gcol]));
    }
    __syncthreads();

    const int b0_ = tid >> 3,         u0_ = tid & 7;
    const int b1_ = (tid + 256) >> 3, u1_ = (tid + 256) & 7;
    float cc0 = 0.f, cc1 = 0.f;

    // per-thread layer-2 biases (constant across steps)
    float bs0[4], bs1[4];
#pragma unroll
    for (int g = 0; g < 4; g++) { bs0[g] = b2[g * HH + u0 + u0_]; bs1[g] = b2[g * HH + u0 + u1_]; }

    float cf[4][4][4], xf[4][4][4];
#pragma unroll
    for (int mt = 0; mt < 4; mt++)
#pragma unroll
        for (int n8 = 0; n8 < 4; n8++)
#pragma unroll
            for (int q = 0; q < 4; q++) { cf[mt][n8][q] = 0.f; xf[mt][n8][q] = 0.f; }

    for (int t = 0; t < TT; t++) {
        const float* hr = hbuf + (t & 1) * (BB * HH);
        float* hw = hbuf + ((t + 1) & 1) * (BB * HH);
        const bool fuse = (t > 0);

        const float* xz = g_xz + (size_t)(t * BB) * G4;
        const float* xp0 = xz + (size_t)b0_ * G4 + u0 + u0_;
        const float* xp1 = xz + (size_t)b1_ * G4 + u0 + u1_;
        float xi0 = __ldg(xp0);            float xi1 = __ldg(xp1);
        float xf0_ = __ldg(xp0 + HH);      float xf1_ = __ldg(xp1 + HH);
        float xg0 = __ldg(xp0 + 2 * HH);   float xg1 = __ldg(xp1 + 2 * HH);
        float xo0 = __ldg(xp0 + 3 * HH);   float xo1 = __ldg(xp1 + 3 * HH);

        fill_slot_f(hr, W2r, 0, u0, Hst, W2s, tid); cp_commit();
        fill_slot_f(hr, W2r, 1, u0, Hst + HSLOT_FLOATS, W2s + WSLOT_FLOATS, tid); cp_commit();

        for (int ch = 0; ch < NCH; ch++) {
            cp_wait1();
            __syncthreads();
            if (ch + 2 < NCH) {
                int fs = (ch + 2) % 3;
                fill_slot_f(hr, W2r, ch + 2, u0, Hst + fs * HSLOT_FLOATS, W2s + fs * WSLOT_FLOATS, tid);
            }
            cp_commit();
            const float* hs = Hst + (ch % 3) * HSLOT_FLOATS;
            const float* ws = W2s + (ch % 3) * WSLOT_FLOATS;

            unsigned a[4][4];
#pragma unroll
            for (int mt = 0; mt < 4; mt++) {
                int r0 = mt * 16 + lr;
                a[mt][0] = __float_as_uint(hs[r0 * HCH_STRIDE + klocal + lc]);
                a[mt][1] = __float_as_uint(hs[(r0 + 8) * HCH_STRIDE + klocal + lc]);
                a[mt][2] = __float_as_uint(hs[r0 * HCH_STRIDE + klocal + lc + 4]);
                a[mt][3] = __float_as_uint(hs[(r0 + 8) * HCH_STRIDE + klocal + lc + 4]);
            }
            int kg = ch * KCH + klocal;
#pragma unroll
            for (int n8 = 0; n8 < 4; n8++) {
                int c0 = n8 * 8 + lr;
                unsigned b0 = __float_as_uint(Us[c0 * US_STRIDE + kg + lc]);
                unsigned b1 = __float_as_uint(Us[c0 * US_STRIDE + kg + lc + 4]);
#pragma unroll
                for (int mt = 0; mt < 4; mt++) mma_tf32(cf[mt][n8], a[mt], b0, b1);
            }
            if (fuse) {
#pragma unroll
                for (int n8 = 0; n8 < 4; n8++) {
                    unsigned b0 = __float_as_uint(ws[(klocal + lc) * W2S_STRIDE + n8 * 8 + lr]);
                    unsigned b1 = __float_as_uint(ws[(klocal + lc + 4) * W2S_STRIDE + n8 * 8 + lr]);
#pragma unroll
                    for (int mt = 0; mt < 4; mt++) mma_tf32(xf[mt][n8], a[mt], b0, b1);
                }
            }
        }

        __syncthreads();   // slots free

        // ---- phase A: z planes -> gates -> h ----
        {
            float* pl = PL + wid * PLANE_FLOATS;
#pragma unroll
            for (int mt = 0; mt < 4; mt++)
#pragma unroll
                for (int n8 = 0; n8 < 4; n8++) {
                    int zr = mt * 16 + lr, zc = n8 * 8 + 2 * lc;
                    pl[zr * 33 + zc]           = cf[mt][n8][0];
                    pl[zr * 33 + zc + 1]       = cf[mt][n8][1];
                    pl[(zr + 8) * 33 + zc]     = cf[mt][n8][2];
                    pl[(zr + 8) * 33 + zc + 1] = cf[mt][n8][3];
                    cf[mt][n8][0] = 0.f; cf[mt][n8][1] = 0.f;
                    cf[mt][n8][2] = 0.f; cf[mt][n8][3] = 0.f;
                }
        }
        __syncthreads();
        {
            float s0 = 0.f, s1 = 0.f, s2 = 0.f, s3 = 0.f;
            float r0 = 0.f, r1 = 0.f, r2 = 0.f, r3 = 0.f;
#pragma unroll
            for (int pw = 0; pw < 8; pw++) {
                const float* pa = PL + pw * PLANE_FLOATS + b0_ * 33;
                const float* pb = PL + pw * PLANE_FLOATS + b1_ * 33;
                s0 += pa[u0_];      s1 += pa[8 + u0_];
                s2 += pa[16 + u0_]; s3 += pa[24 + u0_];
                r0 += pb[u1_];      r1 += pb[8 + u1_];
                r2 += pb[16 + u1_]; r3 += pb[24 + u1_];
            }
            float zi = s0 + xi0, zf = s1 + xf0_, zg = s2 + xg0, zo = s3 + xo0;
            float fi = sigf(zi), ff = sigf(zf), fo = sigf(zo);
            float fg = tanhf(zg);
            float cn = ff * cc0 + fi * fg;
            cc0 = cn;
            hw[(size_t)b0_ * HH + u0 + u0_] = __uint_as_float(f2tf(fo * tanhf(cn)));
            zi = r0 + xi1; zf = r1 + xf1_; zg = r2 + xg1; zo = r3 + xo1;
            fi = sigf(zi); ff = sigf(zf); fo = sigf(zo);
            fg = tanhf(zg);
            cn = ff * cc1 + fi * fg;
            cc1 = cn;
            hw[(size_t)b1_ * HH + u0 + u1_] = __uint_as_float(f2tf(fo * tanhf(cn)));
        }

        // ---- phase B: xz2[t-1] planes -> global ----
        if (fuse) {
            __syncthreads();   // phase-A plane reads done
            {
                float* pl = PL + wid * PLANE_FLOATS;
#pragma unroll
                for (int mt = 0; mt < 4; mt++)
#pragma unroll
                    for (int n8 = 0; n8 < 4; n8++) {
                        int zr = mt * 16 + lr, zc = n8 * 8 + 2 * lc;
                        pl[zr * 33 + zc]           = xf[mt][n8][0];
                        pl[zr * 33 + zc + 1]       = xf[mt][n8][1];
                        pl[(zr + 8) * 33 + zc]     = xf[mt][n8][2];
                        pl[(zr + 8) * 33 + zc + 1] = xf[mt][n8][3];
                        xf[mt][n8][0] = 0.f; xf[mt][n8][1] = 0.f;
                        xf[mt][n8][2] = 0.f; xf[mt][n8][3] = 0.f;
                    }
            }
            __syncthreads();
            {
                float s0 = 0.f, s1 = 0.f, s2 = 0.f, s3 = 0.f;
                float r0 = 0.f, r1 = 0.f, r2 = 0.f, r3 = 0.f;
#pragma unroll
                for (int pw = 0; pw < 8; pw++) {
                    const float* pa = PL + pw * PLANE_FLOATS + b0_ * 33;
                    const float* pb = PL + pw * PLANE_FLOATS + b1_ * 33;
                    s0 += pa[u0_];      s1 += pa[8 + u0_];
                    s2 += pa[16 + u0_]; s3 += pa[24 + u0_];
                    r0 += pb[u1_];      r1 += pb[8 + u1_];
                    r2 += pb[16 + u1_]; r3 += pb[24 + u1_];
                }
                float* o0 = g_xz2 + ((size_t)(t - 1) * BB + b0_) * G4 + u0 + u0_;
                float* o1 = g_xz2 + ((size_t)(t - 1) * BB + b1_) * G4 + u0 + u1_;
                o0[0]      = s0 + bs0[0]; o0[HH]     = s1 + bs0[1];
                o0[2 * HH] = s2 + bs0[2]; o0[3 * HH] = s3 + bs0[3];
                o1[0]      = r0 + bs1[0]; o1[HH]     = r1 + bs1[1];
                o1[2 * HH] = r2 + bs1[2]; o1[3 * HH] = r3 + bs1[3];
            }
        }

        // ---- grid barrier ----
        __threadfence();
        __syncthreads();
        if (tid == 0) flags[blockIdx.x * 32] = (unsigned)(t + 1);
        if (blockIdx.x == 0) {
            if (tid < NCTA) {
                while (flags[tid * 32] < (unsigned)(t + 1)) { }
            }
            __syncthreads();
            if (tid == 0) *epoch = (unsigned)(t + 1);
        }
        if (tid == 0) {
            while (*epoch < (unsigned)(t + 1)) { __nanosleep(32); }
        }
        __syncthreads();
        __threadfence();
    }

    // ---- tail: xz2[TT-1] = h1[TT] @ W2 ----
    {
        const float* hr = hbuf + (TT & 1) * (BB * HH);
        fill_slot_f(hr, W2r, 0, u0, Hst, W2s, tid); cp_commit();
        fill_slot_f(hr, W2r, 1, u0, Hst + HSLOT_FLOATS, W2s + WSLOT_FLOATS, tid); cp_commit();
        for (int ch = 0; ch < NCH; ch++) {
            cp_wait1();
            __syncthreads();
            if (ch + 2 < NCH) {
                int fs = (ch + 2) % 3;
                fill_slot_f(hr, W2r, ch + 2, u0, Hst + fs * HSLOT_FLOATS, W2s + fs * WSLOT_FLOATS, tid);
            }
            cp_commit();
            const float* hs = Hst + (ch % 3) * HSLOT_FLOATS;
            const float* ws = W2s + (ch % 3) * WSLOT_FLOATS;
            unsigned a[4][4];
#pragma unroll
            for (int mt = 0; mt < 4; mt++) {
                int r0 = mt * 16 + lr;
                a[mt][0] = __float_as_uint(hs[r0 * HCH_STRIDE + klocal + lc]);
                a[mt][1] = __float_as_uint(hs[(r0 + 8) * HCH_STRIDE + klocal + lc]);
                a[mt][2] = __float_as_uint(hs[r0 * HCH_STRIDE + klocal + lc + 4]);
                a[mt][3] = __float_as_uint(hs[(r0 + 8) * HCH_STRIDE + klocal + lc + 4]);
            }
#pragma unroll
            for (int n8 = 0; n8 < 4; n8++) {
                unsigned b0 = __float_as_uint(ws[(klocal + lc) * W2S_STRIDE + n8 * 8 + lr]);
                unsigned b1 = __float_as_uint(ws[(klocal + lc + 4) * W2S_STRIDE + n8 * 8 + lr]);
#pragma unroll
                for (int mt = 0; mt < 4; mt++) mma_tf32(xf[mt][n8], a[mt], b0, b1);
            }
        }
        __syncthreads();
        {
            float* pl = PL + wid * PLANE_FLOATS;
#pragma unroll
            for (int mt = 0; mt < 4; mt++)
#pragma unroll
                for (int n8 = 0; n8 < 4; n8++) {
                    int zr = mt * 16 + lr, zc = n8 * 8 + 2 * lc;
                    pl[zr * 33 + zc]           = xf[mt][n8][0];
                    pl[zr * 33 + zc + 1]       = xf[mt][n8][1];
                    pl[(zr + 8) * 33 + zc]     = xf[mt][n8][2];
                    pl[(zr + 8) * 33 + zc + 1] = xf[mt][n8][3];
                }
        }
        __syncthreads();
        {
            float s0 = 0.f, s1 = 0.f, s2 = 0.f, s3 = 0.f;
            float r0 = 0.f, r1 = 0.f, r2 = 0.f, r3 = 0.f;
#pragma unroll
            for (int pw = 0; pw < 8; pw++) {
                const float* pa = PL + pw * PLANE_FLOATS + b0_ * 33;
                const float* pb = PL + pw * PLANE_FLOATS + b1_ * 33;
                s0 += pa[u0_];      s1 += pa[8 + u0_];
                s2 += pa[16 + u0_]; s3 += pa[24 + u0_];
                r0 += pb[u1_];      r1 += pb[8 + u1_];
                r2 += pb[16 + u1_]; r3 += pb[24 + u1_];
            }
            float* o0 = g_xz2 + ((size_t)(TT - 1) * BB + b0_) * G4 + u0 + u0_;
            float* o1 = g_xz2 + ((size_t)(TT - 1) * BB + b1_) * G4 + u0 + u1_;
            o0[0]      = s0 + bs0[0]; o0[HH]     = s1 + bs0[1];
            o0[2 * HH] = s2 + bs0[2]; o0[3 * HH] = s3 + bs0[3];
            o1[0]      = r0 + bs1[0]; o1[HH]     = r1 + bs1[1];
            o1[2 * HH] = r2 + bs1[2]; o1[3 * HH] = r3 + bs1[3];
        }
    }
}

// ================= plain layer-2 scan (split-K, reads g_xz2) =================
__device__ __forceinline__ void lstm_load_chunk(const float* hr, int ch, float* stage, int tid) {
#pragma unroll
    for (int i = 0; i < 4; i++) {
        int idx = i * 256 + tid;
        int r = idx >> 4, s = idx & 15;
        cp16_cg(stage + r * HCH_STRIDE + s * 4, hr + (size_t)r * HH + ch * KCH + s * 4);
    }
}

__global__ void __launch_bounds__(256)
lstm_scan(const float* __restrict__ U)
{
    extern __shared__ float sm[];
    float* Us  = sm;
    float* Hst = Us + 32 * US_STRIDE;

    float* hbuf = g_h2;
    volatile unsigned* flags = g_flag[1];
    volatile unsigned* epoch = &g_epoch[1];

    const int tid = threadIdx.x, lane = tid & 31, wid = tid >> 5;
    const int u0 = blockIdx.x * UPC;
    const int lr = lane >> 2, lc = lane & 3;

    for (int idx = tid; idx < 32 * HH; idx += 256) {
        int k = idx >> 5, c = idx & 31;
        int gcol = (c >> 3) * HH + u0 + (c & 7);
        Us[c * US_STRIDE + k] = __uint_as_float(f2tf(U[(size_t)k * G4 + gcol]));
    }
    __syncthreads();

    const int b0_ = tid >> 3,         u0_ = tid & 7;
    const int b1_ = (tid + 256) >> 3, u1_ = (tid + 256) & 7;
    float cc0 = 0.f, cc1 = 0.f;

    float cf[4][4][4];
#pragma unroll
    for (int mt = 0; mt < 4; mt++)
#pragma unroll
        for (int n8 = 0; n8 < 4; n8++)
#pragma unroll
            for (int q = 0; q < 4; q++) cf[mt][n8][q] = 0.f;

    const int klocal = wid * 8;

    for (int t = 0; t < TT; t++) {
        const float* hr = hbuf + (t & 1) * (BB * HH);
        float* hw = hbuf + ((t + 1) & 1) * (BB * HH);

        const float* xz = g_xz2 + (size_t)(t * BB) * G4;
        const float* xp0 = xz + (size_t)b0_ * G4 + u0 + u0_;
        const float* xp1 = xz + (size_t)b1_ * G4 + u0 + u1_;
        float xi0 = __ldg(xp0);            float xi1 = __ldg(xp1);
        float xf0 = __ldg(xp0 + HH);       float xf1 = __ldg(xp1 + HH);
        float xg0 = __ldg(xp0 + 2 * HH);   float xg1 = __ldg(xp1 + 2 * HH);
        float xo0 = __ldg(xp0 + 3 * HH);   float xo1 = __ldg(xp1 + 3 * HH);

        lstm_load_chunk(hr, 0, Hst + 0 * HSLOT_FLOATS, tid); cp_commit();
        lstm_load_chunk(hr, 1, Hst + 1 * HSLOT_FLOATS, tid); cp_commit();
        lstm_load_chunk(hr, 2, Hst + 2 * HSLOT_FLOATS, tid); cp_commit();

        for (int ch = 0; ch < NCH; ch++) {
            cp_wait2();
            __syncthreads();
            if (ch + 3 < NCH) lstm_load_chunk(hr, ch + 3, Hst + ((ch + 3) & 3) * HSLOT_FLOATS, tid);
            cp_commit();
            const float* hs = Hst + (ch & 3) * HSLOT_FLOATS;

            unsigned a[4][4];
#pragma unroll
            for (int mt = 0; mt < 4; mt++) {
                int r0 = mt * 16 + lr;
                a[mt][0] = __float_as_uint(hs[r0 * HCH_STRIDE + klocal + lc]);
                a[mt][1] = __float_as_uint(hs[(r0 + 8) * HCH_STRIDE + klocal + lc]);
                a[mt][2] = __float_as_uint(hs[r0 * HCH_STRIDE + klocal + lc + 4]);
                a[mt][3] = __float_as_uint(hs[(r0 + 8) * HCH_STRIDE + klocal + lc + 4]);
            }
            int kg = ch * KCH + klocal;
#pragma unroll
            for (int n8 = 0; n8 < 4; n8++) {
                int c0 = n8 * 8 + lr;
                unsigned b0 = __float_as_uint(Us[c0 * US_STRIDE + kg + lc]);
                unsigned b1 = __float_as_uint(Us[c0 * US_STRIDE + kg + lc + 4]);
#pragma unroll
                for (int mt = 0; mt < 4; mt++) mma_tf32(cf[mt][n8], a[mt], b0, b1);
            }
        }

        __syncthreads();
        {
            float* pl = Hst + wid * PLANE_FLOATS;
#pragma unroll
            for (int mt = 0; mt < 4; mt++)
#pragma unroll
                for (int n8 = 0; n8 < 4; n8++) {
                    int zr = mt * 16 + lr, zc = n8 * 8 + 2 * lc;
                    pl[zr * 33 + zc]           = cf[mt][n8][0];
                    pl[zr * 33 + zc + 1]       = cf[mt][n8][1];
                    pl[(zr + 8) * 33 + zc]     = cf[mt][n8][2];
                    pl[(zr + 8) * 33 + zc + 1] = cf[mt][n8][3];
                    cf[mt][n8][0] = 0.f; cf[mt][n8][1] = 0.f;
                    cf[mt][n8][2] = 0.f; cf[mt][n8][3] = 0.f;
                }
        }
        __syncthreads();
        {
            float s0 = 0.f, s1 = 0.f, s2 = 0.f, s3 = 0.f;
            float r0 = 0.f, r1 = 0.f, r2 = 0.f, r3 = 0.f;
#pragma unroll
            for (int pw = 0; pw < 8; pw++) {
                const float* pa = Hst + pw * PLANE_FLOATS + b0_ * 33;
                const float* pb = Hst + pw * PLANE_FLOATS + b1_ * 33;
                s0 += pa[u0_];      s1 += pa[8 + u0_];
                s2 += pa[16 + u0_]; s3 += pa[24 + u0_];
                r0 += pb[u1_];      r1 += pb[8 + u1_];
                r2 += pb[16 + u1_]; r3 += pb[24 + u1_];
            }
            float zi = s0 + xi0, zf = s1 + xf0, zg = s2 + xg0, zo = s3 + xo0;
            float fi = sigf(zi), ff = sigf(zf), fo = sigf(zo);
            float fg = tanhf(zg);
            float cn = ff * cc0 + fi * fg;
            cc0 = cn;
            hw[(size_t)b0_ * HH + u0 + u0_] = __uint_as_float(f2tf(fo * tanhf(cn)));
            zi = r0 + xi1; zf = r1 + xf1; zg = r2 + xg1; zo = r3 + xo1;
            fi = sigf(zi); ff = sigf(zf); fo = sigf(zo);
            fg = tanhf(zg);
            cn = ff * cc1 + fi * fg;
            cc1 = cn;
            hw[(size_t)b1_ * HH + u0 + u1_] = __uint_as_float(f2tf(fo * tanhf(cn)));
        }

        __threadfence();
        __syncthreads();
        if (tid == 0) flags[blockIdx.x * 32] = (unsigned)(t + 1);
        if (blockIdx.x == 0) {
            if (tid < NCTA) {
                while (flags[tid * 32] < (unsigned)(t + 1)) { }
            }
            __syncthreads();
            if (tid == 0) *epoch = (unsigned)(t + 1);
        }
        if (tid == 0) {
            while (*epoch < (unsigned)(t + 1)) { __nanosleep(32); }
        }
        __syncthreads();
        __threadfence();
    }
}

// ---------------- final dense ----------------
__global__ void __launch_bounds__(512)
dense_out(const float* __restrict__ Wd, const float* __restrict__ bd, float* __restrict__ out)
{
    __shared__ float hs[HH];
    int b = blockIdx.x;
    const float* h = g_h2; // h_256 in stage 0 (T even)
    for (int i = threadIdx.x; i < HH; i += 512) hs[i] = h[(size_t)b * HH + i];
    __syncthreads();
    int o = threadIdx.x;
    float acc = bd[o];
#pragma unroll 8
    for (int k = 0; k < HH; k++) acc += hs[k] * Wd[(size_t)k * 512 + o];
    out[(size_t)b * 512 + o] = acc;
}

// ---------------- launch (single stream, serial) ----------------
extern "C" void kernel_launch(void* const* d_in, const int* in_sizes, int n_in,
                              void* d_out, int out_size)
{
    (void)in_sizes; (void)n_in; (void)out_size;
    const float* x  = (const float*)d_in[0];
    const float* W1 = (const float*)d_in[1];
    const float* U1 = (const float*)d_in[2];
    const float* b1 = (const float*)d_in[3];
    const float* W2 = (const float*)d_in[4];
    const float* U2 = (const float*)d_in[5];
    const float* b2 = (const float*)d_in[6];
    const float* Wd = (const float*)d_in[7];
    const float* bd = (const float*)d_in[8];
    float* out = (float*)d_out;

    cudaFuncSetAttribute(gemm_xw,    cudaFuncAttributeMaxDynamicSharedMemorySize, GEMM_SMEM_BYTES);
    cudaFuncSetAttribute(lstm_fused, cudaFuncAttributeMaxDynamicSharedMemorySize, FUSED_SMEM_BYTES);
    cudaFuncSetAttribute(lstm_scan,  cudaFuncAttributeMaxDynamicSharedMemorySize, PLAIN_SMEM_BYTES);

    init_zero<<<128, 256>>>();
    cvt_round<<<1024, 256>>>(x,  0, (BB * TT * DD) / 4);
    cvt_round<<<1024, 256>>>(W1, 1, (DD * G4) / 4);
    cvt_round<<<1024, 256>>>(W2, 2, (HH * G4) / 4);

    dim3 gg(G4 / 64, (BB * TT) / 128);
    gemm_xw<<<gg, 256, GEMM_SMEM_BYTES>>>(b1);
    lstm_fused<<<NCTA, 256, FUSED_SMEM_BYTES>>>(U1, b2);
    lstm_scan<<<NCTA, 256, PLAIN_SMEM_BYTES>>>(U2);

    dense_out<<<BB, 512>>>(Wd, bd, out);
}

// round 10
// speedup vs baseline: 1.7207x; 1.7207x over previous
#include <cuda_runtime.h>
#include <cuda_fp16.h>
#include <cstdint>
#include <cstddef>

// Problem dims
#define BB 64
#define TT 256
#define DD 512
#define HH 1024
#define G4 4096
#define NCTA 128
#define UPC 8
// time chunking for the kernel-level pipeline
#define NTC 8
#define TPC 32
// ---- fp16 GEMM smem (bytes) ----
#define A_ROW_B 80                       // 32 halves + pad
#define W_ROW_B 80
#define GEMM_STAGE_B (128*A_ROW_B + 64*W_ROW_B)   // 15360
#define GEMM_SMEM_BYTES (3*GEMM_STAGE_B)          // 46080
// ---- fp16 scan smem (bytes) ----
#define KCH 128                          // halves per chunk
#define NCH 8
#define HROW_B 272                       // 128 halves + pad
#define HSLOT_B (64*HROW_B)              // 17408
#define UROW_B 2064                      // 1024 halves + pad
#define US_B (32*UROW_B)                 // 66048
#define PLANE_FLOATS (64*33)
#define SCAN_SMEM_BYTES (US_B + 4*HSLOT_B)        // 135680

// ---------------- scratch ----------------
__device__ float    g_xz[(size_t)TT*BB*G4];      // gate pre-acts (fp32), reused by both layers
__device__ __half   g_seq1[(size_t)BB*TT*HH];    // layer-1 output (fp16, rounded)
__device__ __half   g_xh[(size_t)BB*TT*DD];      // x pre-rounded fp16
__device__ __half   g_W1h[(size_t)G4*DD];        // W1 transposed n-major [n][k] fp16
__device__ __half   g_W2h[(size_t)G4*HH];        // W2 transposed n-major
__device__ __half   g_h1[2*BB*HH];
__device__ __half   g_h2[2*BB*HH];
__device__ float    g_c1[BB*HH];                 // cell state (fp32), persists across chunks
__device__ float    g_c2[BB*HH];
__device__ unsigned g_flag[2][NCTA * 32];
__device__ unsigned g_epoch[2];

// ---------------- helpers ----------------
__device__ __forceinline__ void mma_f16(float c[4], const unsigned a[4], unsigned b0, unsigned b1) {
    asm volatile(
        "mma.sync.aligned.m16n8k16.row.col.f32.f16.f16.f32 "
        "{%0,%1,%2,%3}, {%4,%5,%6,%7}, {%8,%9}, {%0,%1,%2,%3};\n"
        : "+f"(c[0]), "+f"(c[1]), "+f"(c[2]), "+f"(c[3])
        : "r"(a[0]), "r"(a[1]), "r"(a[2]), "r"(a[3]), "r"(b0), "r"(b1));
}
__device__ __forceinline__ void cp16_ca(void* smem_dst, const void* gsrc) {
    unsigned d = (unsigned)__cvta_generic_to_shared(smem_dst);
    asm volatile("cp.async.ca.shared.global [%0], [%1], 16;\n" :: "r"(d), "l"(gsrc) : "memory");
}
__device__ __forceinline__ void cp16_cg(void* smem_dst, const void* gsrc) {
    unsigned d = (unsigned)__cvta_generic_to_shared(smem_dst);
    asm volatile("cp.async.cg.shared.global [%0], [%1], 16;\n" :: "r"(d), "l"(gsrc) : "memory");
}
__device__ __forceinline__ void cp_commit() { asm volatile("cp.async.commit_group;\n" ::: "memory"); }
__device__ __forceinline__ void cp_wait1() { asm volatile("cp.async.wait_group 1;\n" ::: "memory"); }
__device__ __forceinline__ void cp_wait2() { asm volatile("cp.async.wait_group 2;\n" ::: "memory"); }
__device__ __forceinline__ float sigf(float x) { return 1.f / (1.f + __expf(-x)); }

// ---------------- init ----------------
__global__ void init_zero() {
    int idx = blockIdx.x * blockDim.x + threadIdx.x;
    int stride = gridDim.x * blockDim.x;
    for (int i = idx; i < 2 * BB * HH; i += stride) {
        g_h1[i] = __float2half_rn(0.f); g_h2[i] = __float2half_rn(0.f);
    }
    for (int i = idx; i < BB * HH; i += stride) { g_c1[i] = 0.f; g_c2[i] = 0.f; }
    for (int i = idx; i < NCTA * 32; i += stride) { g_flag[0][i] = 0u; g_flag[1][i] = 0u; }
    if (idx == 0) { g_epoch[0] = 0u; g_epoch[1] = 0u; }
}

// ---------------- x -> fp16 (elementwise) ----------------
__global__ void __launch_bounds__(256)
cvt_x(const float* __restrict__ src, int n4) {
    int idx = blockIdx.x * blockDim.x + threadIdx.x;
    int stride = gridDim.x * blockDim.x;
    const float4* s4 = (const float4*)src;
    uint2* d4 = (uint2*)g_xh;
    for (int i = idx; i < n4; i += stride) {
        float4 v = s4[i];
        __half2 p0 = __floats2half2_rn(v.x, v.y);
        __half2 p1 = __floats2half2_rn(v.z, v.w);
        uint2 u;
        u.x = *(unsigned*)&p0; u.y = *(unsigned*)&p1;
        d4[i] = u;
    }
}

// ---------------- W [K][G4] fp32 -> [G4][K] fp16 (tiled transpose) ----------------
__global__ void __launch_bounds__(256)
cvt_w_t(const float* __restrict__ src, int which, int K) {
    __shared__ float tile[32][33];
    __half* dst = which ? g_W2h : g_W1h;
    int k0 = blockIdx.y * 32, n0 = blockIdx.x * 32;
    int tx = threadIdx.x & 31, ty = threadIdx.x >> 5;    // ty 0..7
#pragma unroll
    for (int i = 0; i < 32; i += 8)
        tile[ty + i][tx] = src[(size_t)(k0 + ty + i) * G4 + n0 + tx];
    __syncthreads();
#pragma unroll
    for (int i = 0; i < 32; i += 8)
        dst[(size_t)(n0 + ty + i) * K + k0 + tx] = __float2half_rn(tile[tx][ty + i]);
}

// ---------------- fp16 GEMM: g_xz[m][0:4096] = A(m) @ W^T + bias ----------------
// asel 0: A = g_xh [B][T][D]; asel 1: A = g_seq1 [B][T][H]. W in n-major fp16.
__global__ void __launch_bounds__(256)
gemm_xw(int asel, const float* __restrict__ bias, int K, int sAb, int sAt, int m0)
{
    extern __shared__ char smem[];
    const __half* A = asel ? g_seq1 : g_xh;
    const __half* W = asel ? g_W2h : g_W1h;

    const int tid = threadIdx.x;
    const int lane = tid & 31, w = tid >> 5;
    const int wm = w & 3, wn = w >> 2;
    const int bn = blockIdx.x * 64;
    const int bm = m0 + blockIdx.y * 128;
    const int lr = lane >> 2, lc = lane & 3;

    float cf[2][4][4];
#pragma unroll
    for (int i = 0; i < 2; i++)
#pragma unroll
        for (int j = 0; j < 4; j++)
#pragma unroll
            for (int q = 0; q < 4; q++) cf[i][j][q] = 0.f;

    const int KB = K >> 5;

    auto dostage = [&](int slot, int kb) {
        char* As = smem + slot * GEMM_STAGE_B;
        char* Ws = As + 128 * A_ROW_B;
        const int k0 = kb * 32;
#pragma unroll
        for (int i = 0; i < 2; i++) {            // A: 128 rows x 4 segs(16B)
            int idx = i * 256 + tid;
            int r = idx >> 2, s = idx & 3;
            int m = bm + r;
            const __half* src = A + (size_t)(m & 63) * sAb + (size_t)(m >> 6) * sAt + k0 + s * 8;
            cp16_ca(As + r * A_ROW_B + s * 16, src);
        }
        {                                         // W: 64 n-rows x 4 segs
            int r = tid >> 2, s = tid & 3;
            const __half* src = W + (size_t)(bn + r) * K + k0 + s * 8;
            cp16_ca(Ws + r * W_ROW_B + s * 16, src);
        }
    };

    dostage(0, 0); cp_commit();
    dostage(1, 1); cp_commit();

    for (int kb = 0; kb < KB; kb++) {
        cp_wait1();
        __syncthreads();
        if (kb + 2 < KB) dostage((kb + 2) % 3, kb + 2);
        cp_commit();
        const char* as = smem + (kb % 3) * GEMM_STAGE_B;
        const char* ws = as + 128 * A_ROW_B;
#pragma unroll
        for (int k16 = 0; k16 < 2; k16++) {
            int kB = k16 * 32;
            unsigned a[2][4];
#pragma unroll
            for (int mt = 0; mt < 2; mt++) {
                int r0 = wm * 32 + mt * 16 + lr;
                a[mt][0] = *(const unsigned*)(as + r0 * A_ROW_B + kB + lc * 4);
                a[mt][1] = *(const unsigned*)(as + (r0 + 8) * A_ROW_B + kB + lc * 4);
                a[mt][2] = *(const unsigned*)(as + r0 * A_ROW_B + kB + 16 + lc * 4);
                a[mt][3] = *(const unsigned*)(as + (r0 + 8) * A_ROW_B + kB + 16 + lc * 4);
            }
#pragma unroll
            for (int n8 = 0; n8 < 4; n8++) {
                int c0 = wn * 32 + n8 * 8 + lr;
                unsigned b0 = *(const unsigned*)(ws + c0 * W_ROW_B + kB + lc * 4);
                unsigned b1 = *(const unsigned*)(ws + c0 * W_ROW_B + kB + 16 + lc * 4);
#pragma unroll
                for (int mt = 0; mt < 2; mt++) mma_f16(cf[mt][n8], a[mt], b0, b1);
            }
        }
    }

#pragma unroll
    for (int mt = 0; mt < 2; mt++) {
#pragma unroll
        for (int nt = 0; nt < 4; nt++) {
            int gr = bm + wm * 32 + mt * 16 + lr;
            int gc = bn + wn * 32 + nt * 8 + 2 * lc;
            float bv0 = bias[gc], bv1 = bias[gc + 1];
            float2 v;
            v.x = cf[mt][nt][0] + bv0; v.y = cf[mt][nt][1] + bv1;
            *(float2*)&g_xz[(size_t)gr * G4 + gc] = v;
            v.x = cf[mt][nt][2] + bv0; v.y = cf[mt][nt][3] + bv1;
            *(float2*)&g_xz[(size_t)(gr + 8) * G4 + gc] = v;
        }
    }
}

// ---------------- fp16 persistent LSTM scan (split-K, time-chunked) ----------------
__device__ __forceinline__ void lstm_load_chunk(const __half* hr, int ch, char* slot, int tid) {
#pragma unroll
    for (int i = 0; i < 4; i++) {    // 64 rows x 16 segs(16B = 8 halves)
        int idx = i * 256 + tid;
        int r = idx >> 4, s = idx & 15;
        cp16_cg(slot + r * HROW_B + s * 16, hr + (size_t)r * HH + ch * KCH + s * 8);
    }
}

__global__ void __launch_bounds__(256)
lstm_scan(const float* __restrict__ U, int layer, int t0)
{
    extern __shared__ char smem[];
    char* UsB = smem;                 // [32 cols][1024 halves + pad]
    char* Hst = smem + US_B;          // 4 slots of [64][128 halves + pad]
    float* PL = (float*)Hst;          // plane overlay (after slots free)

    __half* hbuf = (layer == 0) ? g_h1 : g_h2;
    float* cbuf = (layer == 0) ? g_c1 : g_c2;
    __half* seqo = (layer == 0) ? g_seq1 : nullptr;
    volatile unsigned* flags = g_flag[layer];
    volatile unsigned* epoch = &g_epoch[layer];

    const int tid = threadIdx.x, lane = tid & 31, wid = tid >> 5;
    const int u0 = blockIdx.x * UPC;
    const int lr = lane >> 2, lc = lane & 3;

    // load U slice transposed+converted: Us[c][k] = half(U[k][gate*HH + u0 + u]), c = gate*8+u
    for (int idx = tid; idx < 32 * HH; idx += 256) {
        int k = idx >> 5, c = idx & 31;
        int gcol = (c >> 3) * HH + u0 + (c & 7);
        ((__half*)UsB)[c * (UROW_B / 2) + k] = __float2half_rn(U[(size_t)k * G4 + gcol]);
    }
    __syncthreads();

    const int b0_ = tid >> 3,         u0_ = tid & 7;
    const int b1_ = (tid + 256) >> 3, u1_ = (tid + 256) & 7;
    float cc0 = cbuf[(size_t)b0_ * HH + u0 + u0_];
    float cc1 = cbuf[(size_t)b1_ * HH + u0 + u1_];

    float cf[4][4][4];
#pragma unroll
    for (int mt = 0; mt < 4; mt++)
#pragma unroll
        for (int n8 = 0; n8 < 4; n8++)
#pragma unroll
            for (int q = 0; q < 4; q++) cf[mt][n8][q] = 0.f;

    const int klB = wid * 32;   // byte offset of this warp's 16-k slice (16 halves)

    for (int t = t0; t < t0 + TPC; t++) {
        const __half* hr = hbuf + (t & 1) * (BB * HH);
        __half* hw = hbuf + ((t + 1) & 1) * (BB * HH);

        const float* xz = g_xz + (size_t)(t * BB) * G4;
        const float* xp0 = xz + (size_t)b0_ * G4 + u0 + u0_;
        const float* xp1 = xz + (size_t)b1_ * G4 + u0 + u1_;
        float xi0 = __ldg(xp0);            float xi1 = __ldg(xp1);
        float xf0 = __ldg(xp0 + HH);       float xf1 = __ldg(xp1 + HH);
        float xg0 = __ldg(xp0 + 2 * HH);   float xg1 = __ldg(xp1 + 2 * HH);
        float xo0 = __ldg(xp0 + 3 * HH);   float xo1 = __ldg(xp1 + 3 * HH);

        lstm_load_chunk(hr, 0, Hst + 0 * HSLOT_B, tid); cp_commit();
        lstm_load_chunk(hr, 1, Hst + 1 * HSLOT_B, tid); cp_commit();
        lstm_load_chunk(hr, 2, Hst + 2 * HSLOT_B, tid); cp_commit();

        for (int ch = 0; ch < NCH; ch++) {
            cp_wait2();
            __syncthreads();
            if (ch + 3 < NCH) lstm_load_chunk(hr, ch + 3, Hst + ((ch + 3) & 3) * HSLOT_B, tid);
            cp_commit();
            const char* hs = Hst + (ch & 3) * HSLOT_B;

            unsigned a[4][4];
#pragma unroll
            for (int mt = 0; mt < 4; mt++) {
                int r0 = mt * 16 + lr;
                a[mt][0] = *(const unsigned*)(hs + r0 * HROW_B + klB + lc * 4);
                a[mt][1] = *(const unsigned*)(hs + (r0 + 8) * HROW_B + klB + lc * 4);
                a[mt][2] = *(const unsigned*)(hs + r0 * HROW_B + klB + 16 + lc * 4);
                a[mt][3] = *(const unsigned*)(hs + (r0 + 8) * HROW_B + klB + 16 + lc * 4);
            }
            int kgB = ch * (KCH * 2) + klB;
#pragma unroll
            for (int n8 = 0; n8 < 4; n8++) {
                int c0 = n8 * 8 + lr;
                unsigned b0 = *(const unsigned*)(UsB + c0 * UROW_B + kgB + lc * 4);
                unsigned b1 = *(const unsigned*)(UsB + c0 * UROW_B + kgB + 16 + lc * 4);
#pragma unroll
                for (int mt = 0; mt < 4; mt++) mma_f16(cf[mt][n8], a[mt], b0, b1);
            }
        }

        __syncthreads();   // slots free -> plane overlay

        {
            float* pl = PL + wid * PLANE_FLOATS;
#pragma unroll
            for (int mt = 0; mt < 4; mt++)
#pragma unroll
                for (int n8 = 0; n8 < 4; n8++) {
                    int zr = mt * 16 + lr, zc = n8 * 8 + 2 * lc;
                    pl[zr * 33 + zc]           = cf[mt][n8][0];
                    pl[zr * 33 + zc + 1]       = cf[mt][n8][1];
                    pl[(zr + 8) * 33 + zc]     = cf[mt][n8][2];
                    pl[(zr + 8) * 33 + zc + 1] = cf[mt][n8][3];
                    cf[mt][n8][0] = 0.f; cf[mt][n8][1] = 0.f;
                    cf[mt][n8][2] = 0.f; cf[mt][n8][3] = 0.f;
                }
        }
        __syncthreads();

        {
            float s0 = 0.f, s1 = 0.f, s2 = 0.f, s3 = 0.f;
            float r0 = 0.f, r1 = 0.f, r2 = 0.f, r3 = 0.f;
#pragma unroll
            for (int pw = 0; pw < 8; pw++) {
                const float* pa = PL + pw * PLANE_FLOATS + b0_ * 33;
                const float* pb = PL + pw * PLANE_FLOATS + b1_ * 33;
                s0 += pa[u0_];      s1 += pa[8 + u0_];
                s2 += pa[16 + u0_]; s3 += pa[24 + u0_];
                r0 += pb[u1_];      r1 += pb[8 + u1_];
                r2 += pb[16 + u1_]; r3 += pb[24 + u1_];
            }
            float zi = s0 + xi0, zf = s1 + xf0, zg = s2 + xg0, zo = s3 + xo0;
            float fi = sigf(zi), ff = sigf(zf), fo = sigf(zo);
            float fg = tanhf(zg);
            float cn = ff * cc0 + fi * fg;
            cc0 = cn;
            __half hnr = __float2half_rn(fo * tanhf(cn));
            hw[(size_t)b0_ * HH + u0 + u0_] = hnr;
            if (seqo) seqo[((size_t)b0_ * TT + t) * HH + u0 + u0_] = hnr;
            zi = r0 + xi1; zf = r1 + xf1; zg = r2 + xg1; zo = r3 + xo1;
            fi = sigf(zi); ff = sigf(zf); fo = sigf(zo);
            fg = tanhf(zg);
            cn = ff * cc1 + fi * fg;
            cc1 = cn;
            hnr = __float2half_rn(fo * tanhf(cn));
            hw[(size_t)b1_ * HH + u0 + u1_] = hnr;
            if (seqo) seqo[((size_t)b1_ * TT + t) * HH + u0 + u1_] = hnr;
        }

        // grid barrier: per-CTA arrive slots + single release epoch
        __threadfence();
        __syncthreads();
        if (tid == 0) flags[blockIdx.x * 32] = (unsigned)(t + 1);
        if (blockIdx.x == 0) {
            if (tid < NCTA) {
                while (flags[tid * 32] < (unsigned)(t + 1)) { }
            }
            __syncthreads();
            if (tid == 0) *epoch = (unsigned)(t + 1);
        }
        if (tid == 0) {
            while (*epoch < (unsigned)(t + 1)) { __nanosleep(32); }
        }
        __syncthreads();
        __threadfence();
    }

    cbuf[(size_t)b0_ * HH + u0 + u0_] = cc0;
    cbuf[(size_t)b1_ * HH + u0 + u1_] = cc1;
}

// ---------------- final dense ----------------
__global__ void __launch_bounds__(512)
dense_out(const float* __restrict__ Wd, const float* __restrict__ bd, float* __restrict__ out)
{
    __shared__ float hs[HH];
    int b = blockIdx.x;
    const __half* h = g_h2;   // h_256 in stage 0 (T even)
    for (int i = threadIdx.x; i < HH; i += 512) hs[i] = __half2float(h[(size_t)b * HH + i]);
    __syncthreads();
    int o = threadIdx.x;
    float acc = bd[o];
#pragma unroll 8
    for (int k = 0; k < HH; k++) acc += hs[k] * Wd[(size_t)k * 512 + o];
    out[(size_t)b * 512 + o] = acc;
}

// ---------------- launch: 3-stream chunked pipeline (graph fork/join via events) ----------------
extern "C" void kernel_launch(void* const* d_in, const int* in_sizes, int n_in,
                              void* d_out, int out_size)
{
    (void)in_sizes; (void)n_in; (void)out_size;
    const float* x  = (const float*)d_in[0];
    const float* W1 = (const float*)d_in[1];
    const float* U1 = (const float*)d_in[2];
    const float* b1 = (const float*)d_in[3];
    const float* W2 = (const float*)d_in[4];
    const float* U2 = (const float*)d_in[5];
    const float* b2 = (const float*)d_in[6];
    const float* Wd = (const float*)d_in[7];
    const float* bd = (const float*)d_in[8];
    float* out = (float*)d_out;

    static cudaStream_t s1 = nullptr, s2 = nullptr;
    static cudaEvent_t evF, evG1[NTC], evL1[NTC], evG2[NTC], evJ1, evJ2;
    if (!s1) {
        cudaStreamCreateWithFlags(&s1, cudaStreamNonBlocking);
        cudaStreamCreateWithFlags(&s2, cudaStreamNonBlocking);
        cudaEventCreateWithFlags(&evF, cudaEventDisableTiming);
        cudaEventCreateWithFlags(&evJ1, cudaEventDisableTiming);
        cudaEventCreateWithFlags(&evJ2, cudaEventDisableTiming);
        for (int k = 0; k < NTC; k++) {
            cudaEventCreateWithFlags(&evG1[k], cudaEventDisableTiming);
            cudaEventCreateWithFlags(&evL1[k], cudaEventDisableTiming);
            cudaEventCreateWithFlags(&evG2[k], cudaEventDisableTiming);
        }
        cudaFuncSetAttribute(gemm_xw,   cudaFuncAttributeMaxDynamicSharedMemorySize, GEMM_SMEM_BYTES);
        cudaFuncSetAttribute(lstm_scan, cudaFuncAttributeMaxDynamicSharedMemorySize, SCAN_SMEM_BYTES);
    }

    // prologue on the main (capturing) stream
    init_zero<<<128, 256>>>();
    cvt_x<<<1024, 256>>>(x, (BB * TT * DD) / 4);
    {
        dim3 gt1(G4 / 32, DD / 32);
        cvt_w_t<<<gt1, 256>>>(W1, 0, DD);
        dim3 gt2(G4 / 32, HH / 32);
        cvt_w_t<<<gt2, 256>>>(W2, 1, HH);
    }

    // fork side streams
    cudaEventRecord(evF, 0);
    cudaStreamWaitEvent(s1, evF, 0);
    cudaStreamWaitEvent(s2, evF, 0);

    dim3 ggc(G4 / 64, (TPC * 64) / 128);

    for (int k = 0; k < NTC; k++) {
        gemm_xw<<<ggc, 256, GEMM_SMEM_BYTES, s1>>>(0, b1, DD, TT * DD, DD, k * TPC * 64);
        cudaEventRecord(evG1[k], s1);
    }

    for (int k = 0; k < NTC; k++) {
        cudaStreamWaitEvent(0, evG1[k], 0);
        lstm_scan<<<NCTA, 256, SCAN_SMEM_BYTES>>>(U1, 0, k * TPC);
        cudaEventRecord(evL1[k], 0);

        cudaStreamWaitEvent(s1, evL1[k], 0);
        gemm_xw<<<ggc, 256, GEMM_SMEM_BYTES, s1>>>(1, b2, HH, TT * HH, HH, k * TPC * 64);
        cudaEventRecord(evG2[k], s1);

        cudaStreamWaitEvent(s2, evG2[k], 0);
        lstm_scan<<<NCTA, 256, SCAN_SMEM_BYTES, s2>>>(U2, 1, k * TPC);
    }

    dense_out<<<BB, 512, 0, s2>>>(Wd, bd, out);

    cudaEventRecord(evJ1, s1);
    cudaEventRecord(evJ2, s2);
    cudaStreamWaitEvent(0, evJ1, 0);
    cudaStreamWaitEvent(0, evJ2, 0);
}